// round 1
// baseline (speedup 1.0000x reference)
#include <cuda_runtime.h>
#include <cstdint>

#define FULL 0xFFFFFFFFu
#define LQ 32      // predicted chars per sample
#define MQ 32      // labels per sample
#define CQ 96      // classes
#define ROWSTRIDE 100   // padded floats per row in smem (conflict-free)
#define SPB 8           // samples (warps) per block
#define MAXB 8192

__device__ float g_per[MAXB];
__device__ float g_non[MAXB];

__global__ void __launch_bounds__(32 * SPB) editloss_main(
    const float* __restrict__ x, const int* __restrict__ y, int B)
{
    extern __shared__ float smem[];
    const int warp = threadIdx.x >> 5;
    const int lane = threadIdx.x & 31;
    const int b = blockIdx.x * SPB + warp;
    if (b >= B) return;

    float* srow = smem + warp * (LQ * ROWSTRIDE);
    uint8_t* mv = (uint8_t*)(smem + SPB * (LQ * ROWSTRIDE)) + warp * (LQ * MQ);

    // ---- Stage logits [32 x 96] into smem, coalesced float4 ----
    const float4* xb4 = (const float4*)(x + (size_t)b * (LQ * CQ));
    #pragma unroll
    for (int it = 0; it < 24; ++it) {
        int f4 = it * 32 + lane;          // 0..767 float4 index
        int row = f4 / 24;                // 96 floats = 24 float4 per row
        int c4  = f4 - row * 24;
        float4 v = xb4[f4];
        *(float4*)(srow + row * ROWSTRIDE + c4 * 4) = v;
    }
    int t_reg = y[b * MQ + lane];         // target char owned by this lane
    __syncwarp();

    // ---- argmax + logsumexp for row = lane ----
    const float4* myrow = (const float4*)(srow + lane * ROWSTRIDE);
    float m = -1e30f; int pred = 0;
    #pragma unroll
    for (int k = 0; k < 24; ++k) {
        float4 v = myrow[k];
        if (v.x > m) { m = v.x; pred = 4 * k + 0; }
        if (v.y > m) { m = v.y; pred = 4 * k + 1; }
        if (v.z > m) { m = v.z; pred = 4 * k + 2; }
        if (v.w > m) { m = v.w; pred = 4 * k + 3; }
    }
    float s = 0.f;
    #pragma unroll
    for (int k = 0; k < 24; ++k) {
        float4 v = myrow[k];
        s += __expf(v.x - m) + __expf(v.y - m) + __expf(v.z - m) + __expf(v.w - m);
    }
    float lse = m + __logf(s);

    // ---- Levenshtein DP, anti-diagonal wavefront. lane l owns row i=l+1 ----
    const int i = lane + 1;
    int prev = 0, prev2 = 0;
    #pragma unroll 1
    for (int k = 2; k <= LQ + MQ; ++k) {
        int j = k - i;
        bool active = (j >= 1) && (j <= MQ);
        int upv = __shfl_up_sync(FULL, prev, 1);   // D[i-1, j]
        int dgv = __shfl_up_sync(FULL, prev2, 1);  // D[i-1, j-1]
        int lfv = prev;                            // D[i, j-1]
        if (lane == 0) { upv = j; dgv = j - 1; }   // D[0,j]=j
        if (j == 1)    { lfv = i; dgv = i - 1; }   // D[i,0]=i
        int tc = __shfl_sync(FULL, t_reg, (j - 1) & 31);
        int cst = (pred != tc) ? 1 : 0;
        int v = min(min(upv, lfv) + 1, dgv + cst);
        if (active) {
            // exact reference backtrace priority: diag, then up, else left
            int code = (dgv + cst == v) ? 0 : ((upv + 1 == v) ? 1 : 2);
            mv[(i - 1) * MQ + (j - 1)] = (uint8_t)code;
            prev2 = prev; prev = v;
        }
    }
    __syncwarp();

    // ---- Backtrace (redundant on all lanes; lane n captures n-th diag pair) ----
    int ii = LQ, jj = MQ, n = 0, my_xi = 0, my_yj = 0;
    #pragma unroll 1
    for (int st = 0; st < LQ + MQ; ++st) {
        int code;
        if (ii > 0) {
            code = (jj > 0) ? (int)mv[(ii - 1) * MQ + (jj - 1)] : 1;
        } else {
            code = (jj > 0) ? 2 : 3;
        }
        if (code == 0) {
            if (n == lane) { my_xi = ii - 1; my_yj = jj - 1; }
            ++n; --ii; --jj;
        } else if (code == 1) { --ii; }
        else if (code == 2)   { --jj; }
    }

    // ---- CE over diagonal steps (logits still live in smem) ----
    int lab    = __shfl_sync(FULL, t_reg, my_yj & 31);
    float lsev = __shfl_sync(FULL, lse,   my_xi & 31);
    float ce = 0.f;
    if (lane < n) ce = lsev - srow[my_xi * ROWSTRIDE + lab];
    #pragma unroll
    for (int o = 16; o; o >>= 1) ce += __shfl_xor_sync(FULL, ce, o);
    if (lane == 0) {
        g_per[b] = (n > 0) ? ce / (float)n : 0.f;
        g_non[b] = (n > 0) ? 1.f : 0.f;
    }
}

__global__ void editloss_reduce(float* __restrict__ out, int B)
{
    __shared__ float ss[256], sc[256];
    float s = 0.f, c = 0.f;
    for (int idx = threadIdx.x; idx < B; idx += 256) {
        s += g_per[idx];
        c += g_non[idx];
    }
    ss[threadIdx.x] = s; sc[threadIdx.x] = c;
    __syncthreads();
    #pragma unroll
    for (int o = 128; o > 0; o >>= 1) {
        if (threadIdx.x < o) {
            ss[threadIdx.x] += ss[threadIdx.x + o];
            sc[threadIdx.x] += sc[threadIdx.x + o];
        }
        __syncthreads();
    }
    if (threadIdx.x == 0) out[0] = ss[0] / sc[0];
}

extern "C" void kernel_launch(void* const* d_in, const int* in_sizes, int n_in,
                              void* d_out, int out_size)
{
    const float* x = (const float*)d_in[0];
    const int*   y = (const int*)d_in[1];
    int B = in_sizes[2];                 // num_chars has B elements
    if (B > MAXB) B = MAXB;

    size_t smem = (size_t)SPB * LQ * ROWSTRIDE * sizeof(float)   // 102400
                + (size_t)SPB * LQ * MQ;                          // + 8192
    cudaFuncSetAttribute(editloss_main,
                         cudaFuncAttributeMaxDynamicSharedMemorySize, (int)smem);

    int blocks = (B + SPB - 1) / SPB;
    editloss_main<<<blocks, 32 * SPB, smem>>>(x, y, B);
    editloss_reduce<<<1, 256>>>((float*)d_out, B);
}